// round 13
// baseline (speedup 1.0000x reference)
#include <cuda_runtime.h>
#include <cuda_fp16.h>

#define B_SZ 4
#define C_DIM 256
#define L_DIM 4096
#define N_GROUPS 32
#define C_PG 8

#define CL (C_DIM * L_DIM)
#define LL (L_DIM * L_DIM)

// ---------------- scratch ----------------
__device__ __half g_ht [B_SZ * CL];          // groupnorm out, [L,C] fp16
__device__ __half g_qk [B_SZ * L_DIM * 512]; // q_t|k_t [L, 512] fp16 (q pre-scaled 1/16)
__device__ __half g_v  [B_SZ * CL];          // v [C,L] fp16
__device__ __half g_h2 [B_SZ * CL];          // h2_t [L,C] fp16
__device__ __half g_s  [B_SZ * LL];          // scores / probs fp16
__device__ __half g_wqk[512 * C_DIM];        // stacked [wq/16 ; wk] fp16
__device__ __half g_wv [C_DIM * C_DIM];
__device__ __half g_wp [C_DIM * C_DIM];
__device__ float  g_bqk[512];                // stacked [qb/16 ; kb]

// ---------------- helpers ----------------
__device__ __forceinline__ unsigned int smem_u32(const void* p) {
    unsigned int a;
    asm("{ .reg .u64 t; cvta.to.shared.u64 t, %1; cvt.u32.u64 %0, t; }"
        : "=r"(a) : "l"(p));
    return a;
}
__device__ __forceinline__ void cpa16(unsigned int dst, const void* src) {
    asm volatile("cp.async.cg.shared.global [%0], [%1], 16;"
                 :: "r"(dst), "l"(src) : "memory");
}
__device__ __forceinline__ void ldsm4(unsigned int* r, unsigned int addr) {
    asm volatile("ldmatrix.sync.aligned.m8n8.x4.shared.b16 {%0,%1,%2,%3}, [%4];"
                 : "=r"(r[0]), "=r"(r[1]), "=r"(r[2]), "=r"(r[3]) : "r"(addr));
}

// ================= GroupNorm -> transposed fp16 =================
__global__ void gn_kernel(const float* __restrict__ x,
                          const float* __restrict__ gamma,
                          const float* __restrict__ beta) {
    int b = blockIdx.x / N_GROUPS;
    int g = blockIdx.x % N_GROUPS;
    const int N = C_PG * L_DIM;
    int gc = g * C_PG;
    const float* xp = x + ((size_t)b * C_DIM + gc) * L_DIM;
    int t = threadIdx.x;

    float s = 0.f, ss = 0.f;
    for (int i = t; i < N; i += 256) {
        float v = xp[i];
        s += v;
        ss = fmaf(v, v, ss);
    }
    #pragma unroll
    for (int o = 16; o; o >>= 1) {
        s  += __shfl_xor_sync(0xffffffffu, s,  o);
        ss += __shfl_xor_sync(0xffffffffu, ss, o);
    }
    __shared__ float shs[8], shss[8];
    if ((t & 31) == 0) { shs[t >> 5] = s; shss[t >> 5] = ss; }
    __syncthreads();
    float ts = 0.f, tss = 0.f;
    #pragma unroll
    for (int w = 0; w < 8; w++) { ts += shs[w]; tss += shss[w]; }

    float mean = ts / (float)N;
    float var  = tss / (float)N - mean * mean;
    float rstd = rsqrtf(var + 1e-6f);

    int c = t & 7;
    float ga = gamma[gc + c], be = beta[gc + c];
    __half* hb = g_ht + (size_t)b * CL + gc + c;
    const float* xc = xp + (size_t)c * L_DIM;
    for (int l = (t >> 3); l < L_DIM; l += 32) {
        float val = (xc[l] - mean) * rstd * ga + be;
        hb[(size_t)l * C_DIM] = __float2half(val);
    }
}

// ================= weight/bias fp32 -> fp16 =================
__global__ void wconv_kernel(const float* __restrict__ qw, const float* __restrict__ kw,
                             const float* __restrict__ vw, const float* __restrict__ pw,
                             const float* __restrict__ qb, const float* __restrict__ kb) {
    int i = blockIdx.x * 256 + threadIdx.x;
    g_wqk[i]                 = __float2half(qw[i] * 0.0625f);
    g_wqk[C_DIM * C_DIM + i] = __float2half(kw[i]);
    g_wv[i]                  = __float2half(vw[i]);
    g_wp[i]                  = __float2half(pw[i]);
    if (i < 256) {
        g_bqk[i]       = qb[i] * 0.0625f;
        g_bqk[256 + i] = kb[i];
    }
}

// ===== fp16 mma.sync GEMM: CTA 128x64, warp 32x32, 3 CTAs/SM =====
// D[m,n] = alpha*(sum_k A[m*lda+k]*B[n*ldb+k] + bias)  (+ fp32 residual)
// 8 warps as 4m x 2n.  K_tile = 64 halves.  m16n8k16.
// BMODE: 0 none, 1 bias[m], 2 bias[n].  OUTF: fp32 out.  RES: add fp32 residual.
#define RWH 72
#define STG2 (192 * RWH)           // halves per stage: A 128 rows + B 64 rows

template<int BMODE, bool OUTF, bool RES>
__global__ __launch_bounds__(256, 3)
void hmma_gemm(const __half* __restrict__ Ag, const __half* __restrict__ Bg,
               const float* __restrict__ bias, const float* __restrict__ Rg,
               void* __restrict__ Cg,
               int K, int lda, int ldb, int ldc, float alpha,
               long sA, long sB, long sR, long sC) {
    extern __shared__ __half dsmh[];

    const int tid = threadIdx.x;
    const int wid = tid >> 5, lane = tid & 31;
    const int gid = lane >> 2, tig = lane & 3;
    const int wm  = wid & 3,  wn  = wid >> 2;     // 4 m-warps x 2 n-warps

    const __half* A = Ag + (long)blockIdx.z * sA + (long)(blockIdx.y * 128) * lda;
    const __half* B = Bg + (long)blockIdx.z * sB + (long)(blockIdx.x * 64) * ldb;

    const unsigned int sbase = smem_u32(dsmh);

    float acc[8][4];
    #pragma unroll
    for (int i = 0; i < 8; i++) {
        acc[i][0] = 0.f; acc[i][1] = 0.f; acc[i][2] = 0.f; acc[i][3] = 0.f;
    }

    const int T = K >> 6;

    auto load_stage = [&](int stage, int t) {
        unsigned int sb = sbase + stage * STG2 * 2;
        const __half* Ak = A + t * 64;
        const __half* Bk = B + t * 64;
        #pragma unroll
        for (int i = 0; i < 4; i++) {            // A: 128 rows x 64 halves
            int e = tid + i * 256;
            int r = e >> 3, k8 = e & 7;
            cpa16(sb + (r * RWH + k8 * 8) * 2, Ak + (long)r * lda + k8 * 8);
        }
        #pragma unroll
        for (int i = 0; i < 2; i++) {            // B: 64 rows x 64 halves
            int e = tid + i * 256;
            int r = e >> 3, k8 = e & 7;
            cpa16(sb + ((128 + r) * RWH + k8 * 8) * 2, Bk + (long)r * ldb + k8 * 8);
        }
        asm volatile("cp.async.commit_group;" ::: "memory");
    };

    load_stage(0, 0);

    // ldmatrix per-lane offsets (bytes): row = lane&15, k-half = (lane>>4)*8
    const unsigned int a_off = ((wm * 32 + (lane & 15)) * RWH + (lane >> 4) * 8) * 2;
    const unsigned int b_off = ((128 + wn * 32 + (lane & 15)) * RWH + (lane >> 4) * 8) * 2;

    for (int t = 0; t < T; t++) {
        int st = t & 1;
        if (t + 1 < T) {
            load_stage(st ^ 1, t + 1);
            asm volatile("cp.async.wait_group 1;" ::: "memory");
        } else {
            asm volatile("cp.async.wait_group 0;" ::: "memory");
        }
        __syncthreads();      // tile t visible

        unsigned int sb = sbase + st * STG2 * 2;
        unsigned int aa = sb + a_off;
        unsigned int bb = sb + b_off;

        #pragma unroll
        for (int kk = 0; kk < 4; kk++) {         // kk*16 within K_tile=64
            unsigned int koff = kk * 16 * 2;
            unsigned int a[2][4];
            ldsm4(a[0], aa + koff);
            ldsm4(a[1], aa + 16 * RWH * 2 + koff);
            unsigned int bfr[2][4];              // bfr[j] covers n = j*16..j*16+15
            ldsm4(bfr[0], bb + koff);
            ldsm4(bfr[1], bb + 16 * RWH * 2 + koff);

            #pragma unroll
            for (int na = 0; na < 4; na++) {
                int j = na >> 1, h = na & 1;
                unsigned int b0 = bfr[j][h];
                unsigned int b1 = bfr[j][h + 2];
                #pragma unroll
                for (int ma = 0; ma < 2; ma++) {
                    float* d = acc[ma * 4 + na];
                    asm volatile(
                        "mma.sync.aligned.m16n8k16.row.col.f32.f16.f16.f32 "
                        "{%0,%1,%2,%3}, {%4,%5,%6,%7}, {%8,%9}, {%0,%1,%2,%3};"
                        : "+f"(d[0]), "+f"(d[1]), "+f"(d[2]), "+f"(d[3])
                        : "r"(a[ma][0]), "r"(a[ma][1]), "r"(a[ma][2]), "r"(a[ma][3]),
                          "r"(b0), "r"(b1));
                }
            }
        }
        __syncthreads();      // all reads of stage st done before it is re-filled
    }

    // ---- epilogue
    long m0 = (long)blockIdx.y * 128 + wm * 32;
    int  n0 = blockIdx.x * 64 + wn * 32;
    #pragma unroll
    for (int ma = 0; ma < 2; ma++) {
        #pragma unroll
        for (int na = 0; na < 4; na++) {
            const float* d = acc[ma * 4 + na];
            long r0 = m0 + ma * 16 + gid;
            int  c  = n0 + na * 8 + tig * 2;
            float b00 = 0.f, b01 = 0.f, b10 = 0.f, b11 = 0.f;
            if (BMODE == 1) {
                b00 = b01 = bias[r0];
                b10 = b11 = bias[r0 + 8];
            } else if (BMODE == 2) {
                float2 bb2 = *reinterpret_cast<const float2*>(bias + c);
                b00 = b10 = bb2.x;
                b01 = b11 = bb2.y;
            }
            float v0 = alpha * (d[0] + b00);
            float v1 = alpha * (d[1] + b01);
            float v2 = alpha * (d[2] + b10);
            float v3 = alpha * (d[3] + b11);
            if (RES) {
                const float* R = Rg + (long)blockIdx.z * sR;
                float2 r1 = *reinterpret_cast<const float2*>(R + r0 * ldc + c);
                float2 r2 = *reinterpret_cast<const float2*>(R + (r0 + 8) * ldc + c);
                v0 += r1.x; v1 += r1.y; v2 += r2.x; v3 += r2.y;
            }
            if (OUTF) {
                float* Cf = (float*)Cg + (long)blockIdx.z * sC;
                *reinterpret_cast<float2*>(Cf + r0 * ldc + c)       = make_float2(v0, v1);
                *reinterpret_cast<float2*>(Cf + (r0 + 8) * ldc + c) = make_float2(v2, v3);
            } else {
                __half* Ch = (__half*)Cg + (long)blockIdx.z * sC;
                *reinterpret_cast<__half2*>(Ch + r0 * ldc + c)       = __floats2half2_rn(v0, v1);
                *reinterpret_cast<__half2*>(Ch + (r0 + 8) * ldc + c) = __floats2half2_rn(v2, v3);
            }
        }
    }
}

// ================= row softmax on fp16 S =================
__global__ void softmax_kernel(__half* __restrict__ S) {
    __half* p = S + (size_t)blockIdx.x * L_DIM;
    int t = threadIdx.x;

    uint4 u[2];
    u[0] = reinterpret_cast<const uint4*>(p)[t];
    u[1] = reinterpret_cast<const uint4*>(p)[t + 256];

    float f[16];
    #pragma unroll
    for (int i = 0; i < 2; i++) {
        const unsigned int* w = reinterpret_cast<const unsigned int*>(&u[i]);
        #pragma unroll
        for (int j = 0; j < 4; j++) {
            float2 ff = __half22float2(*reinterpret_cast<const __half2*>(&w[j]));
            f[i * 8 + j * 2]     = ff.x;
            f[i * 8 + j * 2 + 1] = ff.y;
        }
    }

    float mx = -3.4e38f;
    #pragma unroll
    for (int i = 0; i < 16; i++) mx = fmaxf(mx, f[i]);
    #pragma unroll
    for (int o = 16; o; o >>= 1) mx = fmaxf(mx, __shfl_xor_sync(0xffffffffu, mx, o));

    __shared__ float red[8];
    if ((t & 31) == 0) red[t >> 5] = mx;
    __syncthreads();
    #pragma unroll
    for (int w = 0; w < 8; w++) mx = fmaxf(mx, red[w]);
    __syncthreads();

    float sum = 0.f;
    #pragma unroll
    for (int i = 0; i < 16; i++) {
        f[i] = __expf(f[i] - mx);
        sum += f[i];
    }
    #pragma unroll
    for (int o = 16; o; o >>= 1) sum += __shfl_xor_sync(0xffffffffu, sum, o);
    if ((t & 31) == 0) red[t >> 5] = sum;
    __syncthreads();
    float tot = 0.f;
    #pragma unroll
    for (int w = 0; w < 8; w++) tot += red[w];
    float rinv = 1.0f / tot;

    #pragma unroll
    for (int i = 0; i < 2; i++) {
        unsigned int* w = reinterpret_cast<unsigned int*>(&u[i]);
        #pragma unroll
        for (int j = 0; j < 4; j++) {
            __half2 h2 = __floats2half2_rn(f[i * 8 + j * 2] * rinv,
                                           f[i * 8 + j * 2 + 1] * rinv);
            w[j] = *reinterpret_cast<unsigned int*>(&h2);
        }
    }
    reinterpret_cast<uint4*>(p)[t]       = u[0];
    reinterpret_cast<uint4*>(p)[t + 256] = u[1];
}

// ================= launch =================
extern "C" void kernel_launch(void* const* d_in, const int* in_sizes, int n_in,
                              void* d_out, int out_size) {
    const float* x      = (const float*)d_in[0];
    const float* norm_g = (const float*)d_in[1];
    const float* norm_b = (const float*)d_in[2];
    const float* q_w    = (const float*)d_in[3];
    const float* q_b    = (const float*)d_in[4];
    const float* k_w    = (const float*)d_in[5];
    const float* k_b    = (const float*)d_in[6];
    const float* v_w    = (const float*)d_in[7];
    const float* v_b    = (const float*)d_in[8];
    const float* p_w    = (const float*)d_in[9];
    const float* p_b    = (const float*)d_in[10];
    float* out = (float*)d_out;

    __half *ht, *qk, *v, *h2, *s, *wqk, *wv, *wp;
    float* bqk;
    cudaGetSymbolAddress((void**)&ht,  g_ht);
    cudaGetSymbolAddress((void**)&qk,  g_qk);
    cudaGetSymbolAddress((void**)&v,   g_v);
    cudaGetSymbolAddress((void**)&h2,  g_h2);
    cudaGetSymbolAddress((void**)&s,   g_s);
    cudaGetSymbolAddress((void**)&wqk, g_wqk);
    cudaGetSymbolAddress((void**)&wv,  g_wv);
    cudaGetSymbolAddress((void**)&wp,  g_wp);
    cudaGetSymbolAddress((void**)&bqk, g_bqk);

    const int DSM = 2 * STG2 * 2;   // 55296 B -> 3 CTAs/SM
    cudaFuncSetAttribute(hmma_gemm<2, false, false>, cudaFuncAttributeMaxDynamicSharedMemorySize, DSM);
    cudaFuncSetAttribute(hmma_gemm<1, false, false>, cudaFuncAttributeMaxDynamicSharedMemorySize, DSM);
    cudaFuncSetAttribute(hmma_gemm<0, false, false>, cudaFuncAttributeMaxDynamicSharedMemorySize, DSM);
    cudaFuncSetAttribute(hmma_gemm<1, true,  true >, cudaFuncAttributeMaxDynamicSharedMemorySize, DSM);

    const long SQK = (long)L_DIM * 512;

    // 0) weights -> fp16 (q scaled by 1/16), stacked qk bias
    wconv_kernel<<<C_DIM * C_DIM / 256, 256>>>(q_w, k_w, v_w, p_w, q_b, k_b);

    // 1) group norm -> h_t [L,C] fp16
    gn_kernel<<<B_SZ * N_GROUPS, 256>>>(x, norm_g, norm_b);

    // 2) qk conv: qk[l, 0:512] = h_t[l,:] @ [wq/16 ; wk]^T + [qb/16 ; kb]
    hmma_gemm<2, false, false><<<dim3(8, 32, B_SZ), 256, DSM>>>(
        ht, wqk, bqk, nullptr, qk, C_DIM, C_DIM, C_DIM, 512, 1.0f, CL, 0, 0, SQK);

    //    v[o,l] = sum_c wv[o,c]*h_t[l,c] + vb[o]
    hmma_gemm<1, false, false><<<dim3(64, 2, B_SZ), 256, DSM>>>(
        wv, ht, v_b, nullptr, v, C_DIM, C_DIM, C_DIM, L_DIM, 1.0f, 0, CL, 0, CL);

    // 3) S[i,j] = sum_c qk[i,c]*qk[j,256+c]
    hmma_gemm<0, false, false><<<dim3(64, 32, B_SZ), 256, DSM>>>(
        qk, qk + 256, nullptr, nullptr, s, C_DIM, 512, 512, L_DIM, 1.0f, SQK, SQK, 0, (long)LL);

    // 4) softmax rows
    softmax_kernel<<<B_SZ * L_DIM, 256>>>(s);

    // 5) h2_t[i,c] = sum_j P[i,j]*v[c,j]  -> fp16
    hmma_gemm<0, false, false><<<dim3(4, 32, B_SZ), 256, DSM>>>(
        s, v, nullptr, nullptr, h2, L_DIM, L_DIM, L_DIM, C_DIM, 1.0f, (long)LL, CL, 0, CL);

    // 6) out[o,i] = x[o,i] + sum_c wp[o,c]*h2_t[i,c] + pb[o]
    hmma_gemm<1, true, true><<<dim3(64, 2, B_SZ), 256, DSM>>>(
        wp, h2, p_b, x, out, C_DIM, C_DIM, C_DIM, L_DIM, 1.0f, 0, CL, CL, CL);
}

// round 14
// speedup vs baseline: 1.1870x; 1.1870x over previous
#include <cuda_runtime.h>
#include <cuda_fp16.h>

#define B_SZ 4
#define C_DIM 256
#define L_DIM 4096
#define N_GROUPS 32
#define C_PG 8

#define CL (C_DIM * L_DIM)
#define LL (L_DIM * L_DIM)

// ---------------- scratch ----------------
__device__ __half g_ht [B_SZ * CL];          // groupnorm out, [L,C] fp16
__device__ __half g_qk [B_SZ * L_DIM * 512]; // q_t|k_t [L, 512] fp16 (q pre-scaled 1/16)
__device__ __half g_v  [B_SZ * CL];          // v [C,L] fp16
__device__ __half g_h2 [B_SZ * CL];          // h2_t [L,C] fp16
__device__ __half g_s  [B_SZ * LL];          // exp-scores (unnormalized) fp16
__device__ __half g_wqk[512 * C_DIM];        // stacked [wq/16 ; wk] fp16
__device__ __half g_wv [C_DIM * C_DIM];
__device__ __half g_wp [C_DIM * C_DIM];
__device__ float  g_bqk[512];                // stacked [qb/16 ; kb]
__device__ float  g_z  [B_SZ * L_DIM];       // softmax row sums (fp32)

// ---------------- helpers ----------------
__device__ __forceinline__ unsigned int smem_u32(const void* p) {
    unsigned int a;
    asm("{ .reg .u64 t; cvta.to.shared.u64 t, %1; cvt.u32.u64 %0, t; }"
        : "=r"(a) : "l"(p));
    return a;
}
__device__ __forceinline__ void cpa16(unsigned int dst, const void* src) {
    asm volatile("cp.async.cg.shared.global [%0], [%1], 16;"
                 :: "r"(dst), "l"(src) : "memory");
}
__device__ __forceinline__ void ldsm4(unsigned int* r, unsigned int addr) {
    asm volatile("ldmatrix.sync.aligned.m8n8.x4.shared.b16 {%0,%1,%2,%3}, [%4];"
                 : "=r"(r[0]), "=r"(r[1]), "=r"(r[2]), "=r"(r[3]) : "r"(addr));
}

// ================= GroupNorm -> transposed fp16 =================
__global__ void gn_kernel(const float* __restrict__ x,
                          const float* __restrict__ gamma,
                          const float* __restrict__ beta) {
    int b = blockIdx.x / N_GROUPS;
    int g = blockIdx.x % N_GROUPS;
    const int N = C_PG * L_DIM;
    int gc = g * C_PG;
    const float* xp = x + ((size_t)b * C_DIM + gc) * L_DIM;
    int t = threadIdx.x;

    float s = 0.f, ss = 0.f;
    for (int i = t; i < N; i += 256) {
        float v = xp[i];
        s += v;
        ss = fmaf(v, v, ss);
    }
    #pragma unroll
    for (int o = 16; o; o >>= 1) {
        s  += __shfl_xor_sync(0xffffffffu, s,  o);
        ss += __shfl_xor_sync(0xffffffffu, ss, o);
    }
    __shared__ float shs[8], shss[8];
    if ((t & 31) == 0) { shs[t >> 5] = s; shss[t >> 5] = ss; }
    __syncthreads();
    float ts = 0.f, tss = 0.f;
    #pragma unroll
    for (int w = 0; w < 8; w++) { ts += shs[w]; tss += shss[w]; }

    float mean = ts / (float)N;
    float var  = tss / (float)N - mean * mean;
    float rstd = rsqrtf(var + 1e-6f);

    int c = t & 7;
    float ga = gamma[gc + c], be = beta[gc + c];
    __half* hb = g_ht + (size_t)b * CL + gc + c;
    const float* xc = xp + (size_t)c * L_DIM;
    for (int l = (t >> 3); l < L_DIM; l += 32) {
        float val = (xc[l] - mean) * rstd * ga + be;
        hb[(size_t)l * C_DIM] = __float2half(val);
    }
}

// ================= weight/bias fp32 -> fp16 =================
__global__ void wconv_kernel(const float* __restrict__ qw, const float* __restrict__ kw,
                             const float* __restrict__ vw, const float* __restrict__ pw,
                             const float* __restrict__ qb, const float* __restrict__ kb) {
    int i = blockIdx.x * 256 + threadIdx.x;
    g_wqk[i]                 = __float2half(qw[i] * 0.0625f);
    g_wqk[C_DIM * C_DIM + i] = __float2half(kw[i]);
    g_wv[i]                  = __float2half(vw[i]);
    g_wp[i]                  = __float2half(pw[i]);
    if (i < 256) {
        g_bqk[i]       = qb[i] * 0.0625f;
        g_bqk[256 + i] = kb[i];
    }
}

// ================= fp16 mma.sync GEMM (R11-best config) =================
// D[m,n] = alpha*(sum_k A[m*lda+k]*B[n*ldb+k] + bias)  (+ fp32 residual)
// CTA 128x128, K_tile=64, 8 warps (4m x 2n), warp tile 32x64, m16n8k16.
// BMODE: 0 none, 1 bias[m], 2 bias[n].  OUTF: fp32 out.  RES: add fp32 residual.
// EPI:   0 plain;  1 = store exp(v) fp16 + atomicAdd fp32 row sums to Zg;
//        2 = scale by 1/Zg[row] (per-m) before store.
#define RWH 72
#define STG_H (256 * RWH)

template<int BMODE, bool OUTF, bool RES, int EPI>
__global__ __launch_bounds__(256, 2)
void hmma_gemm(const __half* __restrict__ Ag, const __half* __restrict__ Bg,
               const float* __restrict__ bias, const float* __restrict__ Rg,
               float* __restrict__ Zg, void* __restrict__ Cg,
               int K, int lda, int ldb, int ldc, float alpha,
               long sA, long sB, long sR, long sC) {
    extern __shared__ __half dsmh[];

    const int tid = threadIdx.x;
    const int wid = tid >> 5, lane = tid & 31;
    const int gid = lane >> 2, tig = lane & 3;
    const int wm  = wid & 3,  wn  = wid >> 2;

    const __half* A = Ag + (long)blockIdx.z * sA + (long)(blockIdx.y * 128) * lda;
    const __half* B = Bg + (long)blockIdx.z * sB + (long)(blockIdx.x * 128) * ldb;

    const unsigned int sbase = smem_u32(dsmh);

    float acc[16][4];
    #pragma unroll
    for (int i = 0; i < 16; i++) {
        acc[i][0] = 0.f; acc[i][1] = 0.f; acc[i][2] = 0.f; acc[i][3] = 0.f;
    }

    const int T = K >> 6;

    auto load_stage = [&](int stage, int t) {
        unsigned int sb = sbase + stage * STG_H * 2;
        const __half* Ak = A + t * 64;
        const __half* Bk = B + t * 64;
        #pragma unroll
        for (int i = 0; i < 4; i++) {
            int e = tid + i * 256;
            int r = e >> 3, k8 = e & 7;
            cpa16(sb + (r * RWH + k8 * 8) * 2, Ak + (long)r * lda + k8 * 8);
        }
        #pragma unroll
        for (int i = 0; i < 4; i++) {
            int e = tid + i * 256;
            int r = e >> 3, k8 = e & 7;
            cpa16(sb + ((128 + r) * RWH + k8 * 8) * 2, Bk + (long)r * ldb + k8 * 8);
        }
        asm volatile("cp.async.commit_group;" ::: "memory");
    };

    load_stage(0, 0);

    const unsigned int a_off = ((wm * 32 + (lane & 15)) * RWH + (lane >> 4) * 8) * 2;
    const unsigned int b_off = ((128 + wn * 64 + (lane & 15)) * RWH + (lane >> 4) * 8) * 2;

    for (int t = 0; t < T; t++) {
        int st = t & 1;
        if (t + 1 < T) {
            load_stage(st ^ 1, t + 1);
            asm volatile("cp.async.wait_group 1;" ::: "memory");
        } else {
            asm volatile("cp.async.wait_group 0;" ::: "memory");
        }
        __syncthreads();

        unsigned int sb = sbase + st * STG_H * 2;
        unsigned int aa = sb + a_off;
        unsigned int bb = sb + b_off;

        #pragma unroll
        for (int kk = 0; kk < 4; kk++) {
            unsigned int koff = kk * 16 * 2;
            unsigned int a[2][4];
            ldsm4(a[0], aa + koff);
            ldsm4(a[1], aa + 16 * RWH * 2 + koff);
            unsigned int bfr[4][4];
            #pragma unroll
            for (int j = 0; j < 4; j++)
                ldsm4(bfr[j], bb + j * 16 * RWH * 2 + koff);

            #pragma unroll
            for (int na = 0; na < 8; na++) {
                int j = na >> 1, h = na & 1;
                unsigned int b0 = bfr[j][h];
                unsigned int b1 = bfr[j][h + 2];
                #pragma unroll
                for (int ma = 0; ma < 2; ma++) {
                    float* d = acc[ma * 8 + na];
                    asm volatile(
                        "mma.sync.aligned.m16n8k16.row.col.f32.f16.f16.f32 "
                        "{%0,%1,%2,%3}, {%4,%5,%6,%7}, {%8,%9}, {%0,%1,%2,%3};"
                        : "+f"(d[0]), "+f"(d[1]), "+f"(d[2]), "+f"(d[3])
                        : "r"(a[ma][0]), "r"(a[ma][1]), "r"(a[ma][2]), "r"(a[ma][3]),
                          "r"(b0), "r"(b1));
                }
            }
        }
        __syncthreads();
    }

    // ---- epilogue
    long m0 = (long)blockIdx.y * 128 + wm * 32;
    int  n0 = blockIdx.x * 128 + wn * 64;
    float rs[4] = {0.f, 0.f, 0.f, 0.f};   // EPI==1 row sums: (ma, rowhalf)
    #pragma unroll
    for (int ma = 0; ma < 2; ma++) {
        long r0 = m0 + ma * 16 + gid;
        float rz0 = 1.f, rz1 = 1.f;
        if (EPI == 2) {
            const float* Z = Zg + (long)blockIdx.z * L_DIM;
            rz0 = 1.0f / Z[r0];
            rz1 = 1.0f / Z[r0 + 8];
        }
        #pragma unroll
        for (int na = 0; na < 8; na++) {
            const float* d = acc[ma * 8 + na];
            int c = n0 + na * 8 + tig * 2;
            float b00 = 0.f, b01 = 0.f, b10 = 0.f, b11 = 0.f;
            if (BMODE == 1) {
                b00 = b01 = bias[r0];
                b10 = b11 = bias[r0 + 8];
            } else if (BMODE == 2) {
                float2 bb2 = *reinterpret_cast<const float2*>(bias + c);
                b00 = b10 = bb2.x;
                b01 = b11 = bb2.y;
            }
            float v0 = alpha * (d[0] + b00);
            float v1 = alpha * (d[1] + b01);
            float v2 = alpha * (d[2] + b10);
            float v3 = alpha * (d[3] + b11);
            if (EPI == 1) {
                v0 = __expf(v0); v1 = __expf(v1);
                v2 = __expf(v2); v3 = __expf(v3);
                rs[ma * 2]     += v0 + v1;
                rs[ma * 2 + 1] += v2 + v3;
            } else if (EPI == 2) {
                v0 *= rz0; v1 *= rz0;
                v2 *= rz1; v3 *= rz1;
            }
            if (RES) {
                const float* R = Rg + (long)blockIdx.z * sR;
                float2 r1 = *reinterpret_cast<const float2*>(R + r0 * ldc + c);
                float2 r2 = *reinterpret_cast<const float2*>(R + (r0 + 8) * ldc + c);
                v0 += r1.x; v1 += r1.y; v2 += r2.x; v3 += r2.y;
            }
            if (OUTF) {
                float* Cf = (float*)Cg + (long)blockIdx.z * sC;
                *reinterpret_cast<float2*>(Cf + r0 * ldc + c)       = make_float2(v0, v1);
                *reinterpret_cast<float2*>(Cf + (r0 + 8) * ldc + c) = make_float2(v2, v3);
            } else {
                __half* Ch = (__half*)Cg + (long)blockIdx.z * sC;
                *reinterpret_cast<__half2*>(Ch + r0 * ldc + c)       = __floats2half2_rn(v0, v1);
                *reinterpret_cast<__half2*>(Ch + (r0 + 8) * ldc + c) = __floats2half2_rn(v2, v3);
            }
        }
    }
    if (EPI == 1) {
        // reduce over the 4 tig lanes sharing each row, then one atomic per row
        #pragma unroll
        for (int i = 0; i < 4; i++) {
            rs[i] += __shfl_xor_sync(0xffffffffu, rs[i], 1);
            rs[i] += __shfl_xor_sync(0xffffffffu, rs[i], 2);
        }
        if (tig == 0) {
            float* Z = Zg + (long)blockIdx.z * L_DIM;
            atomicAdd(&Z[m0 + gid],      rs[0]);
            atomicAdd(&Z[m0 + gid + 8],  rs[1]);
            atomicAdd(&Z[m0 + gid + 16], rs[2]);
            atomicAdd(&Z[m0 + gid + 24], rs[3]);
        }
    }
}

// ================= launch =================
extern "C" void kernel_launch(void* const* d_in, const int* in_sizes, int n_in,
                              void* d_out, int out_size) {
    const float* x      = (const float*)d_in[0];
    const float* norm_g = (const float*)d_in[1];
    const float* norm_b = (const float*)d_in[2];
    const float* q_w    = (const float*)d_in[3];
    const float* q_b    = (const float*)d_in[4];
    const float* k_w    = (const float*)d_in[5];
    const float* k_b    = (const float*)d_in[6];
    const float* v_w    = (const float*)d_in[7];
    const float* v_b    = (const float*)d_in[8];
    const float* p_w    = (const float*)d_in[9];
    const float* p_b    = (const float*)d_in[10];
    float* out = (float*)d_out;

    __half *ht, *qk, *v, *h2, *s, *wqk, *wv, *wp;
    float *bqk, *z;
    cudaGetSymbolAddress((void**)&ht,  g_ht);
    cudaGetSymbolAddress((void**)&qk,  g_qk);
    cudaGetSymbolAddress((void**)&v,   g_v);
    cudaGetSymbolAddress((void**)&h2,  g_h2);
    cudaGetSymbolAddress((void**)&s,   g_s);
    cudaGetSymbolAddress((void**)&wqk, g_wqk);
    cudaGetSymbolAddress((void**)&wv,  g_wv);
    cudaGetSymbolAddress((void**)&wp,  g_wp);
    cudaGetSymbolAddress((void**)&bqk, g_bqk);
    cudaGetSymbolAddress((void**)&z,   g_z);

    const int DSM = 2 * STG_H * 2;   // 73728 B, 2 CTAs/SM
    cudaFuncSetAttribute(hmma_gemm<2, false, false, 0>, cudaFuncAttributeMaxDynamicSharedMemorySize, DSM);
    cudaFuncSetAttribute(hmma_gemm<1, false, false, 0>, cudaFuncAttributeMaxDynamicSharedMemorySize, DSM);
    cudaFuncSetAttribute(hmma_gemm<0, false, false, 1>, cudaFuncAttributeMaxDynamicSharedMemorySize, DSM);
    cudaFuncSetAttribute(hmma_gemm<0, false, false, 2>, cudaFuncAttributeMaxDynamicSharedMemorySize, DSM);
    cudaFuncSetAttribute(hmma_gemm<1, true,  true,  0>, cudaFuncAttributeMaxDynamicSharedMemorySize, DSM);

    const long SQK = (long)L_DIM * 512;

    // 0) zero row-sum buffer; weights -> fp16 (q scaled by 1/16)
    cudaMemsetAsync(z, 0, B_SZ * L_DIM * sizeof(float));
    wconv_kernel<<<C_DIM * C_DIM / 256, 256>>>(q_w, k_w, v_w, p_w, q_b, k_b);

    // 1) group norm -> h_t [L,C] fp16
    gn_kernel<<<B_SZ * N_GROUPS, 256>>>(x, norm_g, norm_b);

    // 2) qk conv: qk[l, 0:512] = h_t[l,:] @ [wq/16 ; wk]^T + [qb/16 ; kb]
    hmma_gemm<2, false, false, 0><<<dim3(4, 32, B_SZ), 256, DSM>>>(
        ht, wqk, bqk, nullptr, nullptr, qk, C_DIM, C_DIM, C_DIM, 512, 1.0f, CL, 0, 0, SQK);

    //    v[o,l] = sum_c wv[o,c]*h_t[l,c] + vb[o]
    hmma_gemm<1, false, false, 0><<<dim3(32, 2, B_SZ), 256, DSM>>>(
        wv, ht, v_b, nullptr, nullptr, v, C_DIM, C_DIM, C_DIM, L_DIM, 1.0f, 0, CL, 0, CL);

    // 3) expS[i,j] = exp(sum_c qk[i,c]*qk[j,256+c]); Z[i] += row sums
    hmma_gemm<0, false, false, 1><<<dim3(32, 32, B_SZ), 256, DSM>>>(
        qk, qk + 256, nullptr, nullptr, z, s, C_DIM, 512, 512, L_DIM, 1.0f, SQK, SQK, 0, (long)LL);

    // 4) h2_t[i,c] = (1/Z[i]) * sum_j expS[i,j]*v[c,j]  -> fp16
    hmma_gemm<0, false, false, 2><<<dim3(2, 32, B_SZ), 256, DSM>>>(
        s, v, nullptr, nullptr, z, h2, L_DIM, L_DIM, L_DIM, C_DIM, 1.0f, (long)LL, CL, 0, CL);

    // 5) out[o,i] = x[o,i] + sum_c wp[o,c]*h2_t[i,c] + pb[o]
    hmma_gemm<1, true, true, 0><<<dim3(32, 2, B_SZ), 256, DSM>>>(
        wp, h2, p_b, x, nullptr, out, C_DIM, C_DIM, C_DIM, L_DIM, 1.0f, 0, CL, CL, CL);
}